// round 4
// baseline (speedup 1.0000x reference)
#include <cuda_runtime.h>
#include <math.h>

typedef unsigned long long ull;

// ---------------------------------------------------------------------------
// Scratch (device globals; allocations forbidden).
// VS: max layer output per bound tensor = conv1 out 16*96*15*15 = 345600.
// PS: max im2col patch per tensor = conv2: 16*49*2400 = 1,881,600.
// WT: transposed weights, all 5 convs = 3,725,184 floats.
// ---------------------------------------------------------------------------
#define VS 345600
#define PS 1881600
#define WTS 3725184
__device__ float g_bufA[3 * VS];
__device__ float g_bufB[3 * VS];
__device__ float g_patch[3 * PS];
__device__ float g_wT[WTS];

// wT offsets (floats): [Fp/4][O][4] per layer
#define WOFF1 0
#define WOFF2 14208      // 96*148
#define WOFF3 628608     // +256*2400
#define WOFF4 1513344    // +384*2304
#define WOFF5 2840448    // +384*3456

// ---------------------------------------------------------------------------
// f32x2 packed helpers (sm_103a)
// ---------------------------------------------------------------------------
__device__ __forceinline__ ull pk2(float lo, float hi) {
    ull r; asm("mov.b64 %0, {%1,%2};" : "=l"(r) : "f"(lo), "f"(hi)); return r;
}
__device__ __forceinline__ void upk2(ull v, float& lo, float& hi) {
    asm("mov.b64 {%0,%1}, %2;" : "=f"(lo), "=f"(hi) : "l"(v));
}
__device__ __forceinline__ ull fma2(ull a, ull b, ull c) {
    ull r; asm("fma.rn.f32x2 %0, %1, %2, %3;" : "=l"(r) : "l"(a), "l"(b), "l"(c)); return r;
}
__device__ __forceinline__ ull mul2(ull a, ull b) {
    ull r; asm("mul.rn.f32x2 %0, %1, %2;" : "=l"(r) : "l"(a), "l"(b)); return r;
}
__device__ __forceinline__ float root8(float s) { return sqrtf(sqrtf(sqrtf(s))); }

// ---------------------------------------------------------------------------
// im2col (3 bound tensors), F padded to Fp with zeros.
// patch[(b*L + l)*Fp + f], f = c*K*K + ky*K + kx.
// ---------------------------------------------------------------------------
__global__ void __launch_bounds__(256) im2col_kernel(
    const float* __restrict__ ic, const float* __restrict__ il, const float* __restrict__ ih,
    float* __restrict__ oc, float* __restrict__ ol, float* __restrict__ oh,
    int B, int C, int H, int W, int K, int S, int pad, int Ho, int Wo, int Fp)
{
    const int idx = blockIdx.x * blockDim.x + threadIdx.x;
    const int L = Ho * Wo;
    const int F = C * K * K;
    if (idx >= B * L * Fp) return;
    const int f  = idx % Fp;
    const int bl = idx / Fp;
    const int l  = bl % L;
    const int b  = bl / L;
    float vc = 0.f, vl = 0.f, vh = 0.f;
    if (f < F) {
        const int c  = f / (K * K);
        const int r  = f - c * (K * K);
        const int ky = r / K, kx = r - (r / K) * K;
        const int oy = l / Wo, ox = l - (l / Wo) * Wo;
        const int iy = oy * S - pad + ky;
        const int ix = ox * S - pad + kx;
        if ((unsigned)iy < (unsigned)H && (unsigned)ix < (unsigned)W) {
            const int si = ((b * C + c) * H + iy) * W + ix;
            vc = ic[si]; vl = il[si]; vh = ih[si];
        }
    }
    oc[idx] = vc; ol[idx] = vl; oh[idx] = vh;
}

// ---------------------------------------------------------------------------
// Weight transpose+pad: w[O][F] -> wT[(f/4)][O][4], zero-padded to Fp.
// ---------------------------------------------------------------------------
__global__ void __launch_bounds__(256) wtrans_kernel(
    const float* __restrict__ w, float* __restrict__ wt, int O, int F, int Fp)
{
    const int idx = blockIdx.x * blockDim.x + threadIdx.x;
    if (idx >= O * Fp) return;
    const int f = idx % Fp, o = idx / Fp;
    const float v = (f < F) ? w[o * F + f] : 0.f;
    wt[(f >> 2) * (O * 4) + o * 4 + (f & 3)] = v;
}

// ---------------------------------------------------------------------------
// Packed NormDist (L8) conv, lanes = output channels.
// warp -> (bl, og); lane -> channel o = og*32+lane.
// Sequential loop over Fp/4; weight: one coalesced 16B load per lane per iter;
// patch: warp-uniform broadcast 16B loads. No reductions, no shuffles.
// ---------------------------------------------------------------------------
__global__ void __launch_bounds__(256) normdist_conv_t_kernel(
    const float* __restrict__ pc, const float* __restrict__ pl, const float* __restrict__ ph,
    const float* __restrict__ wT,
    float* __restrict__ outc, float* __restrict__ outl, float* __restrict__ outh,
    int BL, int OG, int Fp, int L, int O)
{
    const int warp = (blockIdx.x * blockDim.x + threadIdx.x) >> 5;
    const int lane = threadIdx.x & 31;
    if (warp >= BL * OG) return;
    const int og = warp % OG;      // consecutive warps share bl -> patch L1 reuse
    const int bl = warp / OG;
    const int o  = og * 32 + lane;

    const int n4 = Fp >> 2;
    const ulonglong2* wp  = (const ulonglong2*)wT + o;            // + i*O per iter
    const ulonglong2* pcp = (const ulonglong2*)(pc + (size_t)bl * Fp);
    const ulonglong2* plp = (const ulonglong2*)(pl + (size_t)bl * Fp);
    const ulonglong2* php = (const ulonglong2*)(ph + (size_t)bl * Fp);

    const ull M1 = 0xBF800000BF800000ULL;  // (-1.0f, -1.0f)

    ull AC = 0, AL = 0, AH = 0;

#define PROC2(W2, VC, VL, VH) {                                        \
        ull dc = fma2(W2, M1, VC);  /* vc - w */                        \
        ull av = fma2(W2, M1, VL);  /* vl - w */                        \
        ull bv = fma2(VH, M1, W2);  /* w - vh */                        \
        ull s  = mul2(dc, dc); s = mul2(s, s); AC = fma2(s, s, AC);     \
        float a0, a1, b0, b1;                                           \
        upk2(av, a0, a1); upk2(bv, b0, b1);                             \
        float dl0 = fmaxf(fmaxf(a0, b0), 0.f);                          \
        float dl1 = fmaxf(fmaxf(a1, b1), 0.f);                          \
        ull dl = pk2(dl0, dl1);                                         \
        s = mul2(dl, dl); s = mul2(s, s); AL = fma2(s, s, AL);          \
        float dh0 = fmaxf(-a0, -b0);  /* = max(|a|,|b|) given vl<=vh */ \
        float dh1 = fmaxf(-a1, -b1);                                    \
        ull dh = pk2(dh0, dh1);                                         \
        s = mul2(dh, dh); s = mul2(s, s); AH = fma2(s, s, AH); }

#pragma unroll 2
    for (int i = 0; i < n4; i++) {
        const ulonglong2 w2 = wp[(size_t)i * O];
        const ulonglong2 c2 = pcp[i];
        const ulonglong2 l2 = plp[i];
        const ulonglong2 h2 = php[i];
        PROC2(w2.x, c2.x, l2.x, h2.x);
        PROC2(w2.y, c2.y, l2.y, h2.y);
    }
#undef PROC2

    float x0, x1, rc, rl, rh;
    upk2(AC, x0, x1); rc = x0 + x1;
    upk2(AL, x0, x1); rl = x0 + x1;
    upk2(AH, x0, x1); rh = x0 + x1;

    const int b = bl / L, l = bl - (bl / L) * L;
    const size_t ob = ((size_t)b * O + o) * L + l;
    outc[ob] = root8(rc);
    outl[ob] = root8(rl);
    outh[ob] = root8(rh);
}

// ---------------------------------------------------------------------------
// 3x3 stride-2 maxpool on all three bound tensors.
// ---------------------------------------------------------------------------
__global__ void __launch_bounds__(256) maxpool_kernel(
    const float* __restrict__ i0, const float* __restrict__ i1, const float* __restrict__ i2,
    float* __restrict__ o0, float* __restrict__ o1, float* __restrict__ o2,
    int NC, int H, int W, int h, int w)
{
    const int i = blockIdx.x * blockDim.x + threadIdx.x;
    if (i >= NC * h * w) return;
    const int x = i % w;
    const int y = (i / w) % h;
    const int n = i / (w * h);
    const int base = (n * H + y * 2) * W + x * 2;
    float m0 = -3.402823466e38f, m1 = m0, m2 = m0;
#pragma unroll
    for (int ky = 0; ky < 3; ky++)
#pragma unroll
        for (int kx = 0; kx < 3; kx++) {
            const int idx = base + ky * W + kx;
            m0 = fmaxf(m0, i0[idx]);
            m1 = fmaxf(m1, i1[idx]);
            m2 = fmaxf(m2, i2[idx]);
        }
    o0[i] = m0; o1[i] = m1; o2[i] = m2;
}

// ---------------------------------------------------------------------------
// Interval-bound linear. Warp per (b,o), float4 over input dim.
// mode 0: relu epilogue; mode 1: final (-c, -u, -l).
// ---------------------------------------------------------------------------
__global__ void __launch_bounds__(256) bound_linear_kernel(
    const float* __restrict__ inc, const float* __restrict__ inl, const float* __restrict__ inh,
    const float* __restrict__ Wm, const float* __restrict__ bias,
    float* __restrict__ outc, float* __restrict__ outl, float* __restrict__ outh,
    int B, int IN, int OUT, int mode)
{
    const int warp = (blockIdx.x * blockDim.x + threadIdx.x) >> 5;
    const int lane = threadIdx.x & 31;
    if (warp >= B * OUT) return;
    const int o = warp % OUT;
    const int b = warp / OUT;

    const float4* c4 = (const float4*)(inc + (size_t)b * IN);
    const float4* l4 = (const float4*)(inl + (size_t)b * IN);
    const float4* h4 = (const float4*)(inh + (size_t)b * IN);
    const float4* w4 = (const float4*)(Wm + (size_t)o * IN);
    const int n4 = IN >> 2;

    float sc = 0.f, sm = 0.f, sr = 0.f;
    for (int k = lane; k < n4; k += 32) {
        const float4 cv = c4[k], lv = l4[k], hv = h4[k], wv = w4[k];
        sc = fmaf(cv.x, wv.x, sc); sc = fmaf(cv.y, wv.y, sc);
        sc = fmaf(cv.z, wv.z, sc); sc = fmaf(cv.w, wv.w, sc);
        sm = fmaf(lv.x + hv.x, wv.x, sm); sm = fmaf(lv.y + hv.y, wv.y, sm);
        sm = fmaf(lv.z + hv.z, wv.z, sm); sm = fmaf(lv.w + hv.w, wv.w, sm);
        sr = fmaf(hv.x - lv.x, fabsf(wv.x), sr); sr = fmaf(hv.y - lv.y, fabsf(wv.y), sr);
        sr = fmaf(hv.z - lv.z, fabsf(wv.z), sr); sr = fmaf(hv.w - lv.w, fabsf(wv.w), sr);
    }
#pragma unroll
    for (int off = 16; off; off >>= 1) {
        sc += __shfl_xor_sync(0xffffffffu, sc, off);
        sm += __shfl_xor_sync(0xffffffffu, sm, off);
        sr += __shfl_xor_sync(0xffffffffu, sr, off);
    }
    if (lane == 0) {
        const float bv  = bias ? bias[o] : 0.f;
        const float oc  = sc + bv;
        const float mid = 0.5f * sm + bv;
        const float rad = 0.5f * sr;
        const size_t idx = (size_t)b * OUT + o;
        if (mode == 0) {
            outc[idx] = fmaxf(oc, 0.f);
            outl[idx] = fmaxf(mid - rad, 0.f);
            outh[idx] = fmaxf(mid + rad, 0.f);
        } else {
            outc[idx] = -oc;            // -center
            outl[idx] = -(mid + rad);   // -upper
            outh[idx] = -(mid - rad);   // -lower
        }
    }
}

// ---------------------------------------------------------------------------
// Host orchestration (graph-capturable: launches only).
// ---------------------------------------------------------------------------
static inline int cdiv(int a, int b) { return (a + b - 1) / b; }

extern "C" void kernel_launch(void* const* d_in, const int* in_sizes, int n_in,
                              void* d_out, int out_size)
{
    const float* x   = (const float*)d_in[0];
    const float* lo  = (const float*)d_in[1];
    const float* hi  = (const float*)d_in[2];
    const float* w1  = (const float*)d_in[3];
    const float* w2  = (const float*)d_in[4];
    const float* w3  = (const float*)d_in[5];
    const float* w4  = (const float*)d_in[6];
    const float* w5  = (const float*)d_in[7];
    const float* fw1 = (const float*)d_in[8];
    const float* fw2 = (const float*)d_in[9];
    const float* fw3 = (const float*)d_in[10];
    const float* fb3 = (const float*)d_in[11];
    float* out = (float*)d_out;

    float *A, *Bf, *P, *WT;
    cudaGetSymbolAddress((void**)&A,  g_bufA);
    cudaGetSymbolAddress((void**)&Bf, g_bufB);
    cudaGetSymbolAddress((void**)&P,  g_patch);
    cudaGetSymbolAddress((void**)&WT, g_wT);
    float *Ac = A,  *Al = A  + VS, *Ah = A  + 2 * VS;
    float *Bc = Bf, *Bl = Bf + VS, *Bh = Bf + 2 * VS;
    float *Pc = P,  *Pl = P  + PS, *Ph = P  + 2 * PS;

    // Transposed/padded weights (every launch; weights are runtime inputs)
    wtrans_kernel<<<cdiv(96 * 148, 256), 256>>>(w1, WT + WOFF1, 96, 147, 148);
    wtrans_kernel<<<cdiv(256 * 2400, 256), 256>>>(w2, WT + WOFF2, 256, 2400, 2400);
    wtrans_kernel<<<cdiv(384 * 2304, 256), 256>>>(w3, WT + WOFF3, 384, 2304, 2304);
    wtrans_kernel<<<cdiv(384 * 3456, 256), 256>>>(w4, WT + WOFF4, 384, 3456, 3456);
    wtrans_kernel<<<cdiv(256 * 3456, 256), 256>>>(w5, WT + WOFF5, 256, 3456, 3456);

#define IM2COL(ic, il, ih, B_, C_, H_, W_, K_, S_, PAD_, HO_, WO_, FP_)            \
    im2col_kernel<<<cdiv((B_) * (HO_) * (WO_) * (FP_), 256), 256>>>(               \
        ic, il, ih, Pc, Pl, Ph, B_, C_, H_, W_, K_, S_, PAD_, HO_, WO_, FP_)

#define CONVT(WOFF_, oc, ol, oh, BL_, O_, FP_, L_)                                 \
    normdist_conv_t_kernel<<<cdiv((BL_) * ((O_) / 32) * 32, 256), 256>>>(          \
        Pc, Pl, Ph, WT + WOFF_, oc, ol, oh, BL_, (O_) / 32, FP_, L_, O_)

    // conv1: [16,3,32,32] -> [16,96,15,15] (k=7,s=2,p=2), Fp=148
    IM2COL(x, lo, hi, 16, 3, 32, 32, 7, 2, 2, 15, 15, 148);
    CONVT(WOFF1, Ac, Al, Ah, 16 * 225, 96, 148, 225);

    // pool1: 15 -> 7
    maxpool_kernel<<<cdiv(16 * 96 * 7 * 7, 256), 256>>>(
        Ac, Al, Ah, Bc, Bl, Bh, 16 * 96, 15, 15, 7, 7);

    // conv2: [16,96,7,7] -> [16,256,7,7] (k=5,s=1,p=2), F=2400
    IM2COL(Bc, Bl, Bh, 16, 96, 7, 7, 5, 1, 2, 7, 7, 2400);
    CONVT(WOFF2, Ac, Al, Ah, 16 * 49, 256, 2400, 49);

    // pool2: 7 -> 3
    maxpool_kernel<<<cdiv(16 * 256 * 3 * 3, 256), 256>>>(
        Ac, Al, Ah, Bc, Bl, Bh, 16 * 256, 7, 7, 3, 3);

    // conv3: [16,256,3,3] -> [16,384,3,3] (k=3,s=1,p=1), F=2304
    IM2COL(Bc, Bl, Bh, 16, 256, 3, 3, 3, 1, 1, 3, 3, 2304);
    CONVT(WOFF3, Ac, Al, Ah, 16 * 9, 384, 2304, 9);

    // conv4: F=3456
    IM2COL(Ac, Al, Ah, 16, 384, 3, 3, 3, 1, 1, 3, 3, 3456);
    CONVT(WOFF4, Bc, Bl, Bh, 16 * 9, 384, 3456, 9);

    // conv5: F=3456
    IM2COL(Bc, Bl, Bh, 16, 384, 3, 3, 3, 1, 1, 3, 3, 3456);
    CONVT(WOFF5, Ac, Al, Ah, 16 * 9, 256, 3456, 9);

    // fc1: 2304 -> 1024 (+relu)
    bound_linear_kernel<<<cdiv(16 * 1024 * 32, 256), 256>>>(
        Ac, Al, Ah, fw1, (const float*)nullptr, Bc, Bl, Bh, 16, 2304, 1024, 0);
    // fc2: 1024 -> 512 (+relu)
    bound_linear_kernel<<<cdiv(16 * 512 * 32, 256), 256>>>(
        Bc, Bl, Bh, fw2, (const float*)nullptr, Ac, Al, Ah, 16, 1024, 512, 0);
    // fc3: 512 -> 10 (+bias): d_out = [-c | -u | -l]
    bound_linear_kernel<<<cdiv(16 * 10 * 32, 256), 256>>>(
        Ac, Al, Ah, fw3, fb3, out, out + 160, out + 320, 16, 512, 10, 1);

#undef IM2COL
#undef CONVT
}

// round 5
// speedup vs baseline: 2.3777x; 2.3777x over previous
#include <cuda_runtime.h>
#include <math.h>

typedef unsigned long long ull;

// ---------------------------------------------------------------------------
// Scratch (device globals; allocations forbidden).
// VS: max layer output per tensor = conv1 out 16*96*15*15 = 345600.
// PS: max im2col patch per tensor = conv2: 16*49*2400 = 1,881,600.
// ---------------------------------------------------------------------------
#define VS 345600
#define PS 1881600
__device__ float g_bufA[3 * VS];
__device__ float g_bufB[3 * VS];
__device__ float g_patch[3 * PS];
__device__ float g_wpad[96 * 148];

// ---------------------------------------------------------------------------
// f32x2 packed helpers (sm_103a)
// ---------------------------------------------------------------------------
__device__ __forceinline__ void upk2(ull v, float& lo, float& hi) {
    asm("mov.b64 {%0,%1}, %2;" : "=f"(lo), "=f"(hi) : "l"(v));
}
__device__ __forceinline__ ull pk2(float lo, float hi) {
    ull r; asm("mov.b64 %0, {%1,%2};" : "=l"(r) : "f"(lo), "f"(hi)); return r;
}
__device__ __forceinline__ ull fma2(ull a, ull b, ull c) {
    ull r; asm("fma.rn.f32x2 %0, %1, %2, %3;" : "=l"(r) : "l"(a), "l"(b), "l"(c)); return r;
}
__device__ __forceinline__ ull mul2(ull a, ull b) {
    ull r; asm("mul.rn.f32x2 %0, %1, %2;" : "=l"(r) : "l"(a), "l"(b)); return r;
}
__device__ __forceinline__ float root8(float s) { return sqrtf(sqrtf(sqrtf(s))); }

// ---------------------------------------------------------------------------
// im2col (3 bound tensors), F padded to Fp with zeros.
// patch[(b*L + l)*Fp + f], f = c*K*K + ky*K + kx.
// ---------------------------------------------------------------------------
__global__ void __launch_bounds__(256) im2col_kernel(
    const float* __restrict__ ic, const float* __restrict__ il, const float* __restrict__ ih,
    float* __restrict__ oc, float* __restrict__ ol, float* __restrict__ oh,
    int B, int C, int H, int W, int K, int S, int pad, int Ho, int Wo, int Fp)
{
    const int idx = blockIdx.x * blockDim.x + threadIdx.x;
    const int L = Ho * Wo;
    const int F = C * K * K;
    if (idx >= B * L * Fp) return;
    const int f  = idx % Fp;
    const int bl = idx / Fp;
    const int l  = bl % L;
    const int b  = bl / L;
    float vc = 0.f, vl = 0.f, vh = 0.f;
    if (f < F) {
        const int c  = f / (K * K);
        const int r  = f - c * (K * K);
        const int ky = r / K, kx = r - (r / K) * K;
        const int oy = l / Wo, ox = l - (l / Wo) * Wo;
        const int iy = oy * S - pad + ky;
        const int ix = ox * S - pad + kx;
        if ((unsigned)iy < (unsigned)H && (unsigned)ix < (unsigned)W) {
            const int si = ((b * C + c) * H + iy) * W + ix;
            vc = ic[si]; vl = il[si]; vh = ih[si];
        }
    }
    oc[idx] = vc; ol[idx] = vl; oh[idx] = vh;
}

// Pad conv1 weights F=147 -> Fp=148 with zeros.
__global__ void __launch_bounds__(256) wpad_kernel(
    const float* __restrict__ w, float* __restrict__ wp, int O, int F, int Fp)
{
    const int idx = blockIdx.x * blockDim.x + threadIdx.x;
    if (idx >= O * Fp) return;
    const int f = idx % Fp, o = idx / Fp;
    wp[idx] = (f < F) ? w[o * F + f] : 0.f;
}

// ---------------------------------------------------------------------------
// Packed NormDist (L8) conv on im2col patches.
// One warp -> TWO (b,l) positions x 4 output channels; lanes split Fp/4.
// 24 packed accumulators; direct 128-bit loads land as f32x2 pairs (no movs).
// ---------------------------------------------------------------------------
__global__ void __launch_bounds__(256) normdist_conv_p_kernel(
    const float* __restrict__ pc, const float* __restrict__ pl, const float* __restrict__ ph,
    const float* __restrict__ wgt,
    float* __restrict__ outc, float* __restrict__ outl, float* __restrict__ outh,
    int BLP, int OG, int Fp, int L, int O)
{
    const int warp = (blockIdx.x * blockDim.x + threadIdx.x) >> 5;
    const int lane = threadIdx.x & 31;
    if (warp >= BLP * OG) return;
    const int og  = warp % OG;      // consecutive warps share bl pair -> L1 patch reuse
    const int blp = warp / OG;
    const int bl0 = blp * 2;

    const int fs = Fp >> 2;  // row length in 16B chunks
    const ulonglong2* pc0 = (const ulonglong2*)(pc + (size_t)bl0 * Fp);
    const ulonglong2* pl0 = (const ulonglong2*)(pl + (size_t)bl0 * Fp);
    const ulonglong2* ph0 = (const ulonglong2*)(ph + (size_t)bl0 * Fp);
    const ulonglong2* wp  = (const ulonglong2*)(wgt + (size_t)(og * 4) * Fp);

    const ull M1 = 0xBF800000BF800000ULL;  // (-1.0f, -1.0f)

    ull A[24];  // [bl(2)][ch(4)][c/l/h(3)]
#pragma unroll
    for (int i = 0; i < 24; i++) A[i] = 0;

#define PROC2(W2, VC, VL, VH, AC, AL, AH) {                            \
        ull dc = fma2(W2, M1, VC);  /* vc - w */                        \
        ull av = fma2(W2, M1, VL);  /* vl - w */                        \
        ull bv = fma2(VH, M1, W2);  /* w - vh */                        \
        ull s  = mul2(dc, dc); s = mul2(s, s); AC = fma2(s, s, AC);     \
        float a0, a1, b0, b1;                                           \
        upk2(av, a0, a1); upk2(bv, b0, b1);                             \
        ull dl = pk2(fmaxf(fmaxf(a0, b0), 0.f),                         \
                     fmaxf(fmaxf(a1, b1), 0.f));                        \
        s = mul2(dl, dl); s = mul2(s, s); AL = fma2(s, s, AL);          \
        ull dh = pk2(fmaxf(fabsf(a0), fabsf(b0)),                       \
                     fmaxf(fabsf(a1), fabsf(b1)));                      \
        s = mul2(dh, dh); s = mul2(s, s); AH = fma2(s, s, AH); }

    for (int q = lane; q < fs; q += 32) {
        const ulonglong2 c0 = pc0[q],      l0 = pl0[q],      h0 = ph0[q];
        const ulonglong2 c1 = pc0[q + fs], l1 = pl0[q + fs], h1 = ph0[q + fs];
#pragma unroll
        for (int ch = 0; ch < 4; ch++) {
            const ulonglong2 w2 = wp[q + (size_t)ch * fs];
            PROC2(w2.x, c0.x, l0.x, h0.x, A[ch * 3], A[ch * 3 + 1], A[ch * 3 + 2]);
            PROC2(w2.y, c0.y, l0.y, h0.y, A[ch * 3], A[ch * 3 + 1], A[ch * 3 + 2]);
            PROC2(w2.x, c1.x, l1.x, h1.x, A[12 + ch * 3], A[12 + ch * 3 + 1], A[12 + ch * 3 + 2]);
            PROC2(w2.y, c1.y, l1.y, h1.y, A[12 + ch * 3], A[12 + ch * 3 + 1], A[12 + ch * 3 + 2]);
        }
    }
#undef PROC2

    float r[24];
#pragma unroll
    for (int i = 0; i < 24; i++) {
        float x0, x1; upk2(A[i], x0, x1); r[i] = x0 + x1;
    }
#pragma unroll
    for (int off = 16; off; off >>= 1)
#pragma unroll
        for (int i = 0; i < 24; i++)
            r[i] += __shfl_xor_sync(0xffffffffu, r[i], off);

    if (lane < 8) {
        const int blx = lane >> 2;          // which of the two positions
        const int ch  = lane & 3;
        const int bl  = bl0 + blx;
        const int b = bl / L, l = bl - (bl / L) * L;
        const size_t ob = ((size_t)b * O + (size_t)og * 4 + ch) * L + l;
        const int v = blx * 12 + ch * 3;
        outc[ob] = root8(r[v]);
        outl[ob] = root8(r[v + 1]);
        outh[ob] = root8(r[v + 2]);
    }
}

// ---------------------------------------------------------------------------
// 3x3 stride-2 maxpool on all three bound tensors.
// ---------------------------------------------------------------------------
__global__ void __launch_bounds__(256) maxpool_kernel(
    const float* __restrict__ i0, const float* __restrict__ i1, const float* __restrict__ i2,
    float* __restrict__ o0, float* __restrict__ o1, float* __restrict__ o2,
    int NC, int H, int W, int h, int w)
{
    const int i = blockIdx.x * blockDim.x + threadIdx.x;
    if (i >= NC * h * w) return;
    const int x = i % w;
    const int y = (i / w) % h;
    const int n = i / (w * h);
    const int base = (n * H + y * 2) * W + x * 2;
    float m0 = -3.402823466e38f, m1 = m0, m2 = m0;
#pragma unroll
    for (int ky = 0; ky < 3; ky++)
#pragma unroll
        for (int kx = 0; kx < 3; kx++) {
            const int idx = base + ky * W + kx;
            m0 = fmaxf(m0, i0[idx]);
            m1 = fmaxf(m1, i1[idx]);
            m2 = fmaxf(m2, i2[idx]);
        }
    o0[i] = m0; o1[i] = m1; o2[i] = m2;
}

// ---------------------------------------------------------------------------
// Interval-bound linear. Warp per (b,o), float4 over input dim.
// mode 0: relu epilogue; mode 1: final (-c, -u, -l).
// ---------------------------------------------------------------------------
__global__ void __launch_bounds__(256) bound_linear_kernel(
    const float* __restrict__ inc, const float* __restrict__ inl, const float* __restrict__ inh,
    const float* __restrict__ Wm, const float* __restrict__ bias,
    float* __restrict__ outc, float* __restrict__ outl, float* __restrict__ outh,
    int B, int IN, int OUT, int mode)
{
    const int warp = (blockIdx.x * blockDim.x + threadIdx.x) >> 5;
    const int lane = threadIdx.x & 31;
    if (warp >= B * OUT) return;
    const int o = warp % OUT;
    const int b = warp / OUT;

    const float4* c4 = (const float4*)(inc + (size_t)b * IN);
    const float4* l4 = (const float4*)(inl + (size_t)b * IN);
    const float4* h4 = (const float4*)(inh + (size_t)b * IN);
    const float4* w4 = (const float4*)(Wm + (size_t)o * IN);
    const int n4 = IN >> 2;

    float sc = 0.f, sm = 0.f, sr = 0.f;
    for (int k = lane; k < n4; k += 32) {
        const float4 cv = c4[k], lv = l4[k], hv = h4[k], wv = w4[k];
        sc = fmaf(cv.x, wv.x, sc); sc = fmaf(cv.y, wv.y, sc);
        sc = fmaf(cv.z, wv.z, sc); sc = fmaf(cv.w, wv.w, sc);
        sm = fmaf(lv.x + hv.x, wv.x, sm); sm = fmaf(lv.y + hv.y, wv.y, sm);
        sm = fmaf(lv.z + hv.z, wv.z, sm); sm = fmaf(lv.w + hv.w, wv.w, sm);
        sr = fmaf(hv.x - lv.x, fabsf(wv.x), sr); sr = fmaf(hv.y - lv.y, fabsf(wv.y), sr);
        sr = fmaf(hv.z - lv.z, fabsf(wv.z), sr); sr = fmaf(hv.w - lv.w, fabsf(wv.w), sr);
    }
#pragma unroll
    for (int off = 16; off; off >>= 1) {
        sc += __shfl_xor_sync(0xffffffffu, sc, off);
        sm += __shfl_xor_sync(0xffffffffu, sm, off);
        sr += __shfl_xor_sync(0xffffffffu, sr, off);
    }
    if (lane == 0) {
        const float bv  = bias ? bias[o] : 0.f;
        const float oc  = sc + bv;
        const float mid = 0.5f * sm + bv;
        const float rad = 0.5f * sr;
        const size_t idx = (size_t)b * OUT + o;
        if (mode == 0) {
            outc[idx] = fmaxf(oc, 0.f);
            outl[idx] = fmaxf(mid - rad, 0.f);
            outh[idx] = fmaxf(mid + rad, 0.f);
        } else {
            outc[idx] = -oc;            // -center
            outl[idx] = -(mid + rad);   // -upper
            outh[idx] = -(mid - rad);   // -lower
        }
    }
}

// ---------------------------------------------------------------------------
// Host orchestration (graph-capturable: launches only).
// ---------------------------------------------------------------------------
static inline int cdiv(int a, int b) { return (a + b - 1) / b; }

extern "C" void kernel_launch(void* const* d_in, const int* in_sizes, int n_in,
                              void* d_out, int out_size)
{
    const float* x   = (const float*)d_in[0];
    const float* lo  = (const float*)d_in[1];
    const float* hi  = (const float*)d_in[2];
    const float* w1  = (const float*)d_in[3];
    const float* w2  = (const float*)d_in[4];
    const float* w3  = (const float*)d_in[5];
    const float* w4  = (const float*)d_in[6];
    const float* w5  = (const float*)d_in[7];
    const float* fw1 = (const float*)d_in[8];
    const float* fw2 = (const float*)d_in[9];
    const float* fw3 = (const float*)d_in[10];
    const float* fb3 = (const float*)d_in[11];
    float* out = (float*)d_out;

    float *A, *Bf, *P, *WP;
    cudaGetSymbolAddress((void**)&A,  g_bufA);
    cudaGetSymbolAddress((void**)&Bf, g_bufB);
    cudaGetSymbolAddress((void**)&P,  g_patch);
    cudaGetSymbolAddress((void**)&WP, g_wpad);
    float *Ac = A,  *Al = A  + VS, *Ah = A  + 2 * VS;
    float *Bc = Bf, *Bl = Bf + VS, *Bh = Bf + 2 * VS;
    float *Pc = P,  *Pl = P  + PS, *Ph = P  + 2 * PS;

#define IM2COL(ic, il, ih, B_, C_, H_, W_, K_, S_, PAD_, HO_, WO_, FP_)            \
    im2col_kernel<<<cdiv((B_) * (HO_) * (WO_) * (FP_), 256), 256>>>(               \
        ic, il, ih, Pc, Pl, Ph, B_, C_, H_, W_, K_, S_, PAD_, HO_, WO_, FP_)

    // warp handles 2 bl x 4 channels
#define CONVP(W_, oc, ol, oh, BL_, O_, FP_, L_)                                    \
    normdist_conv_p_kernel<<<cdiv(((BL_) / 2) * ((O_) / 4) * 32, 256), 256>>>(     \
        Pc, Pl, Ph, W_, oc, ol, oh, (BL_) / 2, (O_) / 4, FP_, L_, O_)

    // conv1: [16,3,32,32] -> [16,96,15,15] (k=7,s=2,p=2), F=147 -> Fp=148
    wpad_kernel<<<cdiv(96 * 148, 256), 256>>>(w1, WP, 96, 147, 148);
    IM2COL(x, lo, hi, 16, 3, 32, 32, 7, 2, 2, 15, 15, 148);
    CONVP(WP, Ac, Al, Ah, 16 * 225, 96, 148, 225);

    // pool1: 15 -> 7
    maxpool_kernel<<<cdiv(16 * 96 * 7 * 7, 256), 256>>>(
        Ac, Al, Ah, Bc, Bl, Bh, 16 * 96, 15, 15, 7, 7);

    // conv2: [16,96,7,7] -> [16,256,7,7] (k=5,s=1,p=2), F=2400
    IM2COL(Bc, Bl, Bh, 16, 96, 7, 7, 5, 1, 2, 7, 7, 2400);
    CONVP(w2, Ac, Al, Ah, 16 * 49, 256, 2400, 49);

    // pool2: 7 -> 3
    maxpool_kernel<<<cdiv(16 * 256 * 3 * 3, 256), 256>>>(
        Ac, Al, Ah, Bc, Bl, Bh, 16 * 256, 7, 7, 3, 3);

    // conv3: [16,256,3,3] -> [16,384,3,3] (k=3,s=1,p=1), F=2304
    IM2COL(Bc, Bl, Bh, 16, 256, 3, 3, 3, 1, 1, 3, 3, 2304);
    CONVP(w3, Ac, Al, Ah, 16 * 9, 384, 2304, 9);

    // conv4: F=3456
    IM2COL(Ac, Al, Ah, 16, 384, 3, 3, 3, 1, 1, 3, 3, 3456);
    CONVP(w4, Bc, Bl, Bh, 16 * 9, 384, 3456, 9);

    // conv5: F=3456
    IM2COL(Bc, Bl, Bh, 16, 384, 3, 3, 3, 1, 1, 3, 3, 3456);
    CONVP(w5, Ac, Al, Ah, 16 * 9, 256, 3456, 9);

    // fc1: 2304 -> 1024 (+relu)
    bound_linear_kernel<<<cdiv(16 * 1024 * 32, 256), 256>>>(
        Ac, Al, Ah, fw1, (const float*)nullptr, Bc, Bl, Bh, 16, 2304, 1024, 0);
    // fc2: 1024 -> 512 (+relu)
    bound_linear_kernel<<<cdiv(16 * 512 * 32, 256), 256>>>(
        Bc, Bl, Bh, fw2, (const float*)nullptr, Ac, Al, Ah, 16, 1024, 512, 0);
    // fc3: 512 -> 10 (+bias): d_out = [-c | -u | -l]
    bound_linear_kernel<<<cdiv(16 * 10 * 32, 256), 256>>>(
        Ac, Al, Ah, fw3, fb3, out, out + 160, out + 320, 16, 512, 10, 1);

#undef IM2COL
#undef CONVP
}